// round 4
// baseline (speedup 1.0000x reference)
#include <cuda_runtime.h>
#include <cuda_bf16.h>
#include <math.h>

// Problem constants
#define T_STEPS   8192
#define N_RES     2048
#define D_IN      64
#define D_OUT     64
#define LEAK      0.3f
#define NOISE_LVL 0.01f

// Persistent scan geometry
#define GRID_P    128            // CTAs, all resident
#define THREADS_P 512            // 16 warps
#define ROWS_CTA  16             // one finalize row per warp

// Static device scratch (no runtime alloc)
__device__ float              g_states[(size_t)T_STEPS * N_RES];  // 64 MB trace
__device__ float              g_drive[(size_t)T_STEPS * N_RES];   // 64 MB u@W_in^T + noise
__device__ unsigned long long g_pack[2][N_RES];                   // {val, epoch} tagged state

// ---------------------------------------------------------------------------
__global__ void init_kernel() {
    int i = blockIdx.x * blockDim.x + threadIdx.x;
    if (i < N_RES) {
        g_pack[0][i] = 0ull;   // version 0: val=0, tag=0
        g_pack[1][i] = 0ull;   // tag 0 != 1, safe
    }
}

// ---------------------------------------------------------------------------
__device__ __forceinline__ unsigned long long ld_rlx64(const unsigned long long* p) {
    unsigned long long v;
    asm volatile("ld.relaxed.gpu.global.b64 %0, [%1];" : "=l"(v) : "l"(p) : "memory");
    return v;
}
__device__ __forceinline__ void st_rlx64(unsigned long long* p, unsigned long long v) {
    asm volatile("st.relaxed.gpu.global.b64 [%0], %1;" :: "l"(p), "l"(v) : "memory");
}
__device__ __forceinline__ void fma2(unsigned long long& acc,
                                     unsigned long long a, unsigned long long b) {
    asm("fma.rn.f32x2 %0, %1, %2, %0;" : "+l"(acc) : "l"(a), "l"(b));
}
__device__ __forceinline__ float lo32(unsigned long long v) {
    return __uint_as_float((unsigned)v);
}
__device__ __forceinline__ float hi32(unsigned long long v) {
    return __uint_as_float((unsigned)(v >> 32));
}

// ---------------------------------------------------------------------------
// drive[t][n] = sum_k u[t][k] * W_in[n][k] + NOISE_LVL * noise[t][n]
__global__ void __launch_bounds__(256)
drive_kernel(const float* __restrict__ u,
             const float* __restrict__ noise,
             const float* __restrict__ W_in)
{
    __shared__ float us[32][64];
    const int tid = threadIdx.x;
    const int n   = blockIdx.x * 256 + tid;
    const int t0  = blockIdx.y * 32;

    for (int i = tid; i < 32 * 64; i += 256)
        us[i >> 6][i & 63] = u[(size_t)(t0 + (i >> 6)) * D_IN + (i & 63)];
    __syncthreads();

    float4 w[16];
#pragma unroll
    for (int j = 0; j < 16; ++j)
        w[j] = *(const float4*)&W_in[(size_t)n * D_IN + j * 4];

#pragma unroll 4
    for (int tt = 0; tt < 32; ++tt) {
        float d = 0.0f;
#pragma unroll
        for (int j = 0; j < 16; ++j) {
            const float4 x = *(const float4*)&us[tt][j * 4];
            d = fmaf(w[j].x, x.x, d);
            d = fmaf(w[j].y, x.y, d);
            d = fmaf(w[j].z, x.z, d);
            d = fmaf(w[j].w, x.w, d);
        }
        const size_t idx = (size_t)(t0 + tt) * N_RES + n;
        g_drive[idx] = fmaf(NOISE_LVL, noise[idx], d);
    }
}

// ---------------------------------------------------------------------------
__global__ void __launch_bounds__(THREADS_P, 1)
reservoir_kernel(const float* __restrict__ W)
{
    __shared__ float s_chunk[ROWS_CTA][128];   // per-warp private staged s-chunk
    __shared__ float psum[2][16][17];          // double-buffered, padded

    const int tid  = threadIdx.x;
    const int lane = tid & 31;
    const int wid  = tid >> 5;                 // 0..15
    const int row  = blockIdx.x * ROWS_CTA + wid;       // finalize row of this warp

    // compute mapping: lane -> (local row, half)
    const int rl    = lane >> 1;               // 0..15
    const int half  = lane & 1;                // 0,1
    const int crow  = blockIdx.x * ROWS_CTA + rl;
    const int kbase = wid * 128 + half * 64;

    // ---- W slice into packed-pair registers: 64 floats = 32 ull ----
    unsigned long long Wp[32];
#pragma unroll
    for (int j = 0; j < 32; ++j)
        Wp[j] = *(const unsigned long long*)&W[(size_t)crow * N_RES + kbase + 2 * j];

    // poll pointers: this lane's 4 tagged elements of chunk wid
    const unsigned long long* pp0 = &g_pack[0][wid * 128 + lane * 4];
    const unsigned long long* pp1 = &g_pack[1][wid * 128 + lane * 4];

    float s_prev = 0.0f;                       // version-0 state of my row (lane 0)
    float drv = 0.0f;
    if (lane == 0) drv = __ldcs(&g_drive[row]);   // drive[0][row]

    for (int t = 0; t < T_STEPS; ++t) {
        const int pb = t & 1;
        const unsigned tg = (unsigned)t;
        const unsigned long long* pp = pb ? pp1 : pp0;

        // ---- poll own 4 tagged words until epoch == t ----
        unsigned long long v0, v1, v2, v3;
        for (;;) {
            v0 = ld_rlx64(pp + 0);
            v1 = ld_rlx64(pp + 1);
            v2 = ld_rlx64(pp + 2);
            v3 = ld_rlx64(pp + 3);
            const bool ok = ((unsigned)(v0 >> 32) == tg) &
                            ((unsigned)(v1 >> 32) == tg) &
                            ((unsigned)(v2 >> 32) == tg) &
                            ((unsigned)(v3 >> 32) == tg);
            if (__all_sync(0xffffffffu, ok)) break;
        }
        // ---- stage values into this warp's private chunk ----
        float4 sv;
        sv.x = lo32(v0); sv.y = lo32(v1); sv.z = lo32(v2); sv.w = lo32(v3);
        *(float4*)&s_chunk[wid][lane * 4] = sv;
        __syncwarp();

        // ---- packed dot: 64 k-values for row rl over this warp's chunk ----
        unsigned long long acc0 = 0ull, acc1 = 0ull, acc2 = 0ull, acc3 = 0ull;
        const float* sp = &s_chunk[wid][half * 64];
#pragma unroll
        for (int j = 0; j < 16; j += 2) {
            const ulonglong2 xa = *(const ulonglong2*)&sp[j * 4];
            fma2(acc0, Wp[2 * j + 0], xa.x);
            fma2(acc1, Wp[2 * j + 1], xa.y);
            const ulonglong2 xb = *(const ulonglong2*)&sp[j * 4 + 4];
            fma2(acc2, Wp[2 * j + 2], xb.x);
            fma2(acc3, Wp[2 * j + 3], xb.y);
        }
        float part = (lo32(acc0) + hi32(acc0)) + (lo32(acc1) + hi32(acc1))
                   + (lo32(acc2) + hi32(acc2)) + (lo32(acc3) + hi32(acc3));
        part += __shfl_xor_sync(0xffffffffu, part, 1);   // combine halves
        if (half == 0)
            psum[pb][wid][rl] = part;

        __syncthreads();   // the ONLY full barrier per step

        // ---- distributed finalize: warp w handles row w ----
        float p = (lane < 16) ? psum[pb][lane][wid] : 0.0f;
        p += __shfl_xor_sync(0xffffffffu, p, 8);
        p += __shfl_xor_sync(0xffffffffu, p, 4);
        p += __shfl_xor_sync(0xffffffffu, p, 2);
        p += __shfl_xor_sync(0xffffffffu, p, 1);
        if (lane == 0) {
            const float ns = tanhf(drv + p);
            const float sn = (1.0f - LEAK) * s_prev + LEAK * ns;
            s_prev = sn;
            g_states[(size_t)t * N_RES + row] = sn;
            const unsigned long long pkt =
                ((unsigned long long)(unsigned)(t + 1) << 32) |
                (unsigned long long)__float_as_uint(sn);
            st_rlx64(&g_pack[(t + 1) & 1][row], pkt);
            const int tn = (t + 1 < T_STEPS) ? t + 1 : t;
            drv = __ldcs(&g_drive[(size_t)tn * N_RES + row]);   // prefetch next drive
        }
    }
}

// ---------------------------------------------------------------------------
// Readout: out[T, 64] = states[T, 2048] @ w_out[64, 2048]^T + b_out
__global__ void __launch_bounds__(256)
readout_kernel(const float* __restrict__ wout,
               const float* __restrict__ bout,
               float* __restrict__ out)
{
    __shared__ float As[64][65];
    __shared__ float Bs[64][65];

    const int t0  = blockIdx.x * 64;
    const int tid = threadIdx.x;
    const int tx  = tid & 15;
    const int ty  = tid >> 4;

    float acc[4][4];
#pragma unroll
    for (int i = 0; i < 4; ++i)
#pragma unroll
        for (int j = 0; j < 4; ++j) acc[i][j] = 0.0f;

    for (int k0 = 0; k0 < N_RES; k0 += 64) {
#pragma unroll
        for (int i = tid; i < 1024; i += 256) {
            const int r  = i >> 4;
            const int c4 = (i & 15) * 4;
            const float4 v = *(const float4*)&g_states[(size_t)(t0 + r) * N_RES + k0 + c4];
            As[c4 + 0][r] = v.x; As[c4 + 1][r] = v.y;
            As[c4 + 2][r] = v.z; As[c4 + 3][r] = v.w;
            const float4 w = *(const float4*)&wout[(size_t)r * N_RES + k0 + c4];
            Bs[c4 + 0][r] = w.x; Bs[c4 + 1][r] = w.y;
            Bs[c4 + 2][r] = w.z; Bs[c4 + 3][r] = w.w;
        }
        __syncthreads();

#pragma unroll
        for (int kk = 0; kk < 64; ++kk) {
            float a[4], b[4];
#pragma unroll
            for (int j = 0; j < 4; ++j) { a[j] = As[kk][4 * ty + j]; b[j] = Bs[kk][4 * tx + j]; }
#pragma unroll
            for (int i = 0; i < 4; ++i)
#pragma unroll
                for (int j = 0; j < 4; ++j) acc[i][j] = fmaf(a[i], b[j], acc[i][j]);
        }
        __syncthreads();
    }

#pragma unroll
    for (int i = 0; i < 4; ++i)
#pragma unroll
        for (int j = 0; j < 4; ++j)
            out[(size_t)(t0 + 4 * ty + i) * D_OUT + 4 * tx + j] = acc[i][j] + bout[4 * tx + j];
}

// ---------------------------------------------------------------------------
extern "C" void kernel_launch(void* const* d_in, const int* in_sizes, int n_in,
                              void* d_out, int out_size)
{
    const float* u     = (const float*)d_in[0];
    const float* noise = (const float*)d_in[1];
    const float* W_in  = (const float*)d_in[2];
    const float* W     = (const float*)d_in[3];
    const float* w_out = (const float*)d_in[4];
    const float* b_out = (const float*)d_in[5];
    float*       out   = (float*)d_out;

    init_kernel<<<8, 256>>>();
    {
        dim3 g(N_RES / 256, T_STEPS / 32);
        drive_kernel<<<g, 256>>>(u, noise, W_in);
    }
    reservoir_kernel<<<GRID_P, THREADS_P>>>(W);
    readout_kernel<<<T_STEPS / 64, 256>>>(w_out, b_out, out);
}

// round 8
// speedup vs baseline: 3.4487x; 3.4487x over previous
#include <cuda_runtime.h>
#include <cuda_bf16.h>
#include <math.h>

// Problem constants
#define T_STEPS   8192
#define N_RES     2048
#define D_IN      64
#define D_OUT     64
#define LEAK      0.3f
#define NOISE_LVL 0.01f

// Persistent scan geometry
#define GRID_P    128            // CTAs, all resident, occ=1
#define THREADS_P 512            // 16 warps
#define ROWS_CTA  16

// Static device scratch (no runtime alloc)
__device__ float        g_states[(size_t)T_STEPS * N_RES];  // 64 MB trace
__device__ float        g_drive[(size_t)T_STEPS * N_RES];   // 64 MB u@W_in^T + noise
__device__ float        g_s[2][N_RES];                      // double-buffered state
__device__ unsigned int g_flag[GRID_P * 32];                // per-CTA epoch, 128B apart

// ---------------------------------------------------------------------------
__global__ void init_kernel() {
    int i = blockIdx.x * blockDim.x + threadIdx.x;
    if (i < N_RES)  g_s[0][i] = 0.0f;
    if (i < GRID_P) g_flag[i * 32] = 0u;
}

// ---------------------------------------------------------------------------
__device__ __forceinline__ unsigned int ld_acq(const unsigned int* p) {
    unsigned int v;
    asm volatile("ld.acquire.gpu.global.u32 %0, [%1];" : "=r"(v) : "l"(p) : "memory");
    return v;
}
__device__ __forceinline__ void st_rel(unsigned int* p, unsigned int v) {
    asm volatile("st.release.gpu.global.u32 [%0], %1;" :: "l"(p), "r"(v) : "memory");
}
__device__ __forceinline__ void fma2(unsigned long long& acc,
                                     unsigned long long a, unsigned long long b) {
    asm("fma.rn.f32x2 %0, %1, %2, %0;" : "+l"(acc) : "l"(a), "l"(b));
}
__device__ __forceinline__ float lo32(unsigned long long v) {
    return __uint_as_float((unsigned)v);
}
__device__ __forceinline__ float hi32(unsigned long long v) {
    return __uint_as_float((unsigned)(v >> 32));
}
// clamped fast tanh: (e^{2x}-1)/(e^{2x}+1), |2x| clamped to 30 (no overflow)
__device__ __forceinline__ float fast_tanh(float x) {
    float x2 = fminf(fmaxf(2.0f * x, -30.0f), 30.0f);
    float e  = __expf(x2);
    return __fdividef(e - 1.0f, e + 1.0f);
}

// ---------------------------------------------------------------------------
// drive[t][n] = sum_k u[t][k] * W_in[n][k] + NOISE_LVL * noise[t][n]
__global__ void __launch_bounds__(256)
drive_kernel(const float* __restrict__ u,
             const float* __restrict__ noise,
             const float* __restrict__ W_in)
{
    __shared__ float us[32][64];
    const int tid = threadIdx.x;
    const int n   = blockIdx.x * 256 + tid;
    const int t0  = blockIdx.y * 32;

    for (int i = tid; i < 32 * 64; i += 256)
        us[i >> 6][i & 63] = u[(size_t)(t0 + (i >> 6)) * D_IN + (i & 63)];
    __syncthreads();

    float4 w[16];
#pragma unroll
    for (int j = 0; j < 16; ++j)
        w[j] = *(const float4*)&W_in[(size_t)n * D_IN + j * 4];

#pragma unroll 4
    for (int tt = 0; tt < 32; ++tt) {
        float d = 0.0f;
#pragma unroll
        for (int j = 0; j < 16; ++j) {
            const float4 x = *(const float4*)&us[tt][j * 4];
            d = fmaf(w[j].x, x.x, d);
            d = fmaf(w[j].y, x.y, d);
            d = fmaf(w[j].z, x.z, d);
            d = fmaf(w[j].w, x.w, d);
        }
        const size_t idx = (size_t)(t0 + tt) * N_RES + n;
        g_drive[idx] = fmaf(NOISE_LVL, noise[idx], d);
    }
}

// ---------------------------------------------------------------------------
__global__ void __launch_bounds__(THREADS_P, 1)
reservoir_kernel(const float* __restrict__ W)
{
    __shared__ float s_ext[2][N_RES];      // double-buffered staged state
    __shared__ float psum[2][ROWS_CTA][4]; // cross-warp partials (cols 0,1 used)

    const int tid  = threadIdx.x;
    const int lane = tid & 31;
    const int wid  = tid >> 5;             // 0..15

    // ---- compute mapping: row-pair g, k-pair lane kp, half h ----
    const int g  = tid >> 6;               // 0..7 : rows {2g, 2g+1}
    const int kp = tid & 63;               // 0..63: k-pairs {2kp + 128i}
    const int h  = wid & 1;                // which half of the 64 kp lanes
    const int row0 = blockIdx.x * ROWS_CTA + 2 * g;

    // ---- W slices as packed pairs: 2 rows x 16 ull each ----
    unsigned long long W0[16], W1[16];
#pragma unroll
    for (int i = 0; i < 16; ++i) {
        W0[i] = *(const unsigned long long*)&W[(size_t)row0 * N_RES + 2 * kp + 128 * i];
        W1[i] = *(const unsigned long long*)&W[(size_t)(row0 + 1) * N_RES + 2 * kp + 128 * i];
    }

    // ---- staging mapping: warp wid stages elements [128*wid, 128*wid+128) ----
    const int elem = wid * 128 + lane * 4;
    // lane polls the flag of the CTA that PRODUCES its own 4 staged elements
    const unsigned int* my_flag = &g_flag[(unsigned)((8 * wid + (lane >> 2)) << 5)];

    // ---- tail state (warp 0, lanes 0..15): row = bid*16 + lane ----
    const int myrow = blockIdx.x * ROWS_CTA + lane;   // valid for lane<16
    float s_prev = 0.0f;
    float drv = 0.0f;
    if (wid == 0 && lane < 16) drv = __ldcs(&g_drive[myrow]);   // drive[0][row]

    for (int t = 0; t < T_STEPS; ++t) {
        const int buf = t & 1;

        // ---- poll producer flags for this warp's chunk (>= t) ----
        {
            const unsigned int need = (unsigned int)t;
            while (!__all_sync(0xffffffffu, ld_acq(my_flag) >= need)) { /* spin */ }
        }
        // ---- stage this warp's 128-element s chunk ----
        {
            const float4 sv = __ldcg((const float4*)&g_s[buf][elem]);
            *(float4*)&s_ext[buf][elem] = sv;
        }
        __syncthreads();   // bar #1: full s staged

        // ---- packed 2-row dot slice: 16 LDS.64 + 32 FFMA2 ----
        unsigned long long a0 = 0ull, a1 = 0ull, b0 = 0ull, b1 = 0ull;
#pragma unroll
        for (int i = 0; i < 16; i += 2) {
            const unsigned long long x =
                *(const unsigned long long*)&s_ext[buf][2 * kp + 128 * i];
            fma2(a0, W0[i], x);
            fma2(a1, W1[i], x);
            const unsigned long long y =
                *(const unsigned long long*)&s_ext[buf][2 * kp + 128 * (i + 1)];
            fma2(b0, W0[i + 1], y);
            fma2(b1, W1[i + 1], y);
        }
        float p0 = (lo32(a0) + hi32(a0)) + (lo32(b0) + hi32(b0));
        float p1 = (lo32(a1) + hi32(a1)) + (lo32(b1) + hi32(b1));
#pragma unroll
        for (int off = 16; off > 0; off >>= 1) {
            p0 += __shfl_xor_sync(0xffffffffu, p0, off);
            p1 += __shfl_xor_sync(0xffffffffu, p1, off);
        }
        if (lane == 0) {
            psum[buf][2 * g + 0][h] = p0;
            psum[buf][2 * g + 1][h] = p1;
        }
        __syncthreads();   // bar #2: psums visible

        // ---- warp 0: finalize 16 rows, publish state + flag ----
        if (wid == 0) {
            if (lane < 16) {
                const float dot = psum[buf][lane][0] + psum[buf][lane][1];
                const float ns  = fast_tanh(drv + dot);
                const float sn  = (1.0f - LEAK) * s_prev + LEAK * ns;
                s_prev = sn;
                g_s[buf ^ 1][myrow] = sn;
                g_states[(size_t)t * N_RES + myrow] = sn;
            }
            __syncwarp();
            if (lane == 0)
                st_rel(&g_flag[(unsigned)(blockIdx.x << 5)], (unsigned int)(t + 1));
            if (lane < 16) {   // prefetch next drive AFTER the release store
                const int tn = (t + 1 < T_STEPS) ? t + 1 : t;
                drv = __ldcs(&g_drive[(size_t)tn * N_RES + myrow]);
            }
        }
    }
}

// ---------------------------------------------------------------------------
// Readout: out[T, 64] = states[T, 2048] @ w_out[64, 2048]^T + b_out
__global__ void __launch_bounds__(256)
readout_kernel(const float* __restrict__ wout,
               const float* __restrict__ bout,
               float* __restrict__ out)
{
    __shared__ float As[64][65];
    __shared__ float Bs[64][65];

    const int t0  = blockIdx.x * 64;
    const int tid = threadIdx.x;
    const int tx  = tid & 15;
    const int ty  = tid >> 4;

    float acc[4][4];
#pragma unroll
    for (int i = 0; i < 4; ++i)
#pragma unroll
        for (int j = 0; j < 4; ++j) acc[i][j] = 0.0f;

    for (int k0 = 0; k0 < N_RES; k0 += 64) {
#pragma unroll
        for (int i = tid; i < 1024; i += 256) {
            const int r  = i >> 4;
            const int c4 = (i & 15) * 4;
            const float4 v = *(const float4*)&g_states[(size_t)(t0 + r) * N_RES + k0 + c4];
            As[c4 + 0][r] = v.x; As[c4 + 1][r] = v.y;
            As[c4 + 2][r] = v.z; As[c4 + 3][r] = v.w;
            const float4 w = *(const float4*)&wout[(size_t)r * N_RES + k0 + c4];
            Bs[c4 + 0][r] = w.x; Bs[c4 + 1][r] = w.y;
            Bs[c4 + 2][r] = w.z; Bs[c4 + 3][r] = w.w;
        }
        __syncthreads();

#pragma unroll
        for (int kk = 0; kk < 64; ++kk) {
            float a[4], b[4];
#pragma unroll
            for (int j = 0; j < 4; ++j) { a[j] = As[kk][4 * ty + j]; b[j] = Bs[kk][4 * tx + j]; }
#pragma unroll
            for (int i = 0; i < 4; ++i)
#pragma unroll
                for (int j = 0; j < 4; ++j) acc[i][j] = fmaf(a[i], b[j], acc[i][j]);
        }
        __syncthreads();
    }

#pragma unroll
    for (int i = 0; i < 4; ++i)
#pragma unroll
        for (int j = 0; j < 4; ++j)
            out[(size_t)(t0 + 4 * ty + i) * D_OUT + 4 * tx + j] = acc[i][j] + bout[4 * tx + j];
}

// ---------------------------------------------------------------------------
extern "C" void kernel_launch(void* const* d_in, const int* in_sizes, int n_in,
                              void* d_out, int out_size)
{
    const float* u     = (const float*)d_in[0];
    const float* noise = (const float*)d_in[1];
    const float* W_in  = (const float*)d_in[2];
    const float* W     = (const float*)d_in[3];
    const float* w_out = (const float*)d_in[4];
    const float* b_out = (const float*)d_in[5];
    float*       out   = (float*)d_out;

    init_kernel<<<8, 256>>>();
    {
        dim3 g(N_RES / 256, T_STEPS / 32);
        drive_kernel<<<g, 256>>>(u, noise, W_in);
    }
    reservoir_kernel<<<GRID_P, THREADS_P>>>(W);
    readout_kernel<<<T_STEPS / 64, 256>>>(w_out, b_out, out);
}

// round 12
// speedup vs baseline: 4.9261x; 1.4284x over previous
#include <cuda_runtime.h>
#include <cuda_bf16.h>
#include <math.h>

// Problem constants
#define T_STEPS   8192
#define N_RES     2048
#define D_IN      64
#define D_OUT     64
#define LEAK      0.3f
#define NOISE_LVL 0.01f

// Persistent scan geometry
#define GRID_P    128            // CTAs, all resident, occ=1
#define THREADS_P 512            // 16 warps
#define ROWS_CTA  16

// Static device scratch (no runtime alloc)
__device__ float              g_states[(size_t)T_STEPS * N_RES];  // 64 MB trace
__device__ float              g_drive[(size_t)T_STEPS * N_RES];   // 64 MB u@W_in^T + noise
// Tagged state exchange: one 128B line per CTA, 16 x {f32 val, u32 tag} words.
__device__ unsigned long long g_line[2][GRID_P][ROWS_CTA];

// ---------------------------------------------------------------------------
__global__ void init_kernel() {
    int i = blockIdx.x * blockDim.x + threadIdx.x;
    if (i < 2 * GRID_P * ROWS_CTA)
        (&g_line[0][0][0])[i] = 0ull;   // tag=0, val=0  (s_0 = 0, epoch 0)
}

// ---------------------------------------------------------------------------
__device__ __forceinline__ void ld_rlx_v2(const unsigned long long* p,
                                          unsigned long long& a, unsigned long long& b) {
    asm volatile("ld.relaxed.gpu.global.v2.b64 {%0,%1}, [%2];"
                 : "=l"(a), "=l"(b) : "l"(p) : "memory");
}
__device__ __forceinline__ void st_rlx64(unsigned long long* p, unsigned long long v) {
    asm volatile("st.relaxed.gpu.global.b64 [%0], %1;" :: "l"(p), "l"(v) : "memory");
}
__device__ __forceinline__ void fma2(unsigned long long& acc,
                                     unsigned long long a, unsigned long long b) {
    asm("fma.rn.f32x2 %0, %1, %2, %0;" : "+l"(acc) : "l"(a), "l"(b));
}
__device__ __forceinline__ float lo32(unsigned long long v) {
    return __uint_as_float((unsigned)v);
}
__device__ __forceinline__ float hi32(unsigned long long v) {
    return __uint_as_float((unsigned)(v >> 32));
}
// clamped fast tanh: (e^{2x}-1)/(e^{2x}+1), |2x| clamped (no overflow)
__device__ __forceinline__ float fast_tanh(float x) {
    float x2 = fminf(fmaxf(2.0f * x, -30.0f), 30.0f);
    float e  = __expf(x2);
    return __fdividef(e - 1.0f, e + 1.0f);
}

// ---------------------------------------------------------------------------
// drive[t][n] = sum_k u[t][k] * W_in[n][k] + NOISE_LVL * noise[t][n]
__global__ void __launch_bounds__(256)
drive_kernel(const float* __restrict__ u,
             const float* __restrict__ noise,
             const float* __restrict__ W_in)
{
    __shared__ float us[32][64];
    const int tid = threadIdx.x;
    const int n   = blockIdx.x * 256 + tid;
    const int t0  = blockIdx.y * 32;

    for (int i = tid; i < 32 * 64; i += 256)
        us[i >> 6][i & 63] = u[(size_t)(t0 + (i >> 6)) * D_IN + (i & 63)];
    __syncthreads();

    float4 w[16];
#pragma unroll
    for (int j = 0; j < 16; ++j)
        w[j] = *(const float4*)&W_in[(size_t)n * D_IN + j * 4];

#pragma unroll 4
    for (int tt = 0; tt < 32; ++tt) {
        float d = 0.0f;
#pragma unroll
        for (int j = 0; j < 16; ++j) {
            const float4 x = *(const float4*)&us[tt][j * 4];
            d = fmaf(w[j].x, x.x, d);
            d = fmaf(w[j].y, x.y, d);
            d = fmaf(w[j].z, x.z, d);
            d = fmaf(w[j].w, x.w, d);
        }
        const size_t idx = (size_t)(t0 + tt) * N_RES + n;
        g_drive[idx] = fmaf(NOISE_LVL, noise[idx], d);
    }
}

// ---------------------------------------------------------------------------
__global__ void __launch_bounds__(THREADS_P, 1)
reservoir_kernel(const float* __restrict__ W)
{
    __shared__ float s_ext[2][N_RES];      // double-buffered staged state
    __shared__ float psum[2][ROWS_CTA][4]; // cross-warp partials (cols 0,1 used)

    const int tid  = threadIdx.x;
    const int lane = tid & 31;
    const int wid  = tid >> 5;             // 0..15

    // ---- compute mapping: row-pair g, k-pair lane kp, half h ----
    const int g  = tid >> 6;               // 0..7 : rows {2g, 2g+1}
    const int kp = tid & 63;               // 0..63: k-pairs {2kp + 128i}
    const int h  = wid & 1;
    const int row0 = blockIdx.x * ROWS_CTA + 2 * g;

    // ---- W slices as packed pairs: 2 rows x 16 ull each ----
    unsigned long long W0[16], W1[16];
#pragma unroll
    for (int i = 0; i < 16; ++i) {
        W0[i] = *(const unsigned long long*)&W[(size_t)row0 * N_RES + 2 * kp + 128 * i];
        W1[i] = *(const unsigned long long*)&W[(size_t)(row0 + 1) * N_RES + 2 * kp + 128 * i];
    }

    // ---- staging mapping: warp wid stages elements [128*wid, 128*wid+128) ----
    // lane covers producer CTA p's words [widx, widx+4)  (= rows 16p+widx..+3)
    const int p    = 8 * wid + (lane >> 2);    // producer CTA
    const int widx = 4 * (lane & 3);           // word index within its line
    const unsigned long long* src0 = &g_line[0][p][widx];
    const unsigned long long* src1 = &g_line[1][p][widx];
    float* dst0 = &s_ext[0][16 * p + widx];
    float* dst1 = &s_ext[1][16 * p + widx];

    // ---- tail state (warp 0, lanes 0..15): row = bid*16 + lane ----
    const int myrow = blockIdx.x * ROWS_CTA + lane;   // valid for lane<16
    float s_prev = 0.0f;
    float drv = 0.0f;
    if (wid == 0 && lane < 16) drv = __ldcs(&g_drive[myrow]);   // drive[0][row]

    for (int t = 0; t < T_STEPS; ++t) {
        const int buf = t & 1;
        const unsigned need = (unsigned)t;
        const unsigned long long* src = buf ? src1 : src0;

        // ---- poll tagged words: data arrives WITH the tag ----
        unsigned long long v0, v1, v2, v3;
        for (;;) {
            ld_rlx_v2(src + 0, v0, v1);
            ld_rlx_v2(src + 2, v2, v3);
            const bool ok = ((int)((unsigned)(v0 >> 32) - need) >= 0) &
                            ((int)((unsigned)(v1 >> 32) - need) >= 0) &
                            ((int)((unsigned)(v2 >> 32) - need) >= 0) &
                            ((int)((unsigned)(v3 >> 32) - need) >= 0);
            if (__all_sync(0xffffffffu, ok)) break;
        }
        // ---- stage the 4 carried values ----
        {
            float4 sv;
            sv.x = lo32(v0); sv.y = lo32(v1); sv.z = lo32(v2); sv.w = lo32(v3);
            *(float4*)(buf ? dst1 : dst0) = sv;
        }
        __syncthreads();   // bar #1: full s staged

        // ---- packed 2-row dot slice: LDS.64 + FFMA2 ----
        unsigned long long a0 = 0ull, a1 = 0ull, b0 = 0ull, b1 = 0ull;
#pragma unroll
        for (int i = 0; i < 16; i += 2) {
            const unsigned long long x =
                *(const unsigned long long*)&s_ext[buf][2 * kp + 128 * i];
            fma2(a0, W0[i], x);
            fma2(a1, W1[i], x);
            const unsigned long long y =
                *(const unsigned long long*)&s_ext[buf][2 * kp + 128 * (i + 1)];
            fma2(b0, W0[i + 1], y);
            fma2(b1, W1[i + 1], y);
        }
        float p0 = (lo32(a0) + hi32(a0)) + (lo32(b0) + hi32(b0));
        float p1 = (lo32(a1) + hi32(a1)) + (lo32(b1) + hi32(b1));
#pragma unroll
        for (int off = 16; off > 0; off >>= 1) {
            p0 += __shfl_xor_sync(0xffffffffu, p0, off);
            p1 += __shfl_xor_sync(0xffffffffu, p1, off);
        }
        if (lane == 0) {
            psum[buf][2 * g + 0][h] = p0;
            psum[buf][2 * g + 1][h] = p1;
        }
        __syncthreads();   // bar #2: psums visible

        // ---- warp 0: finalize 16 rows, publish tagged line ----
        if (wid == 0) {
            if (lane < 16) {
                const float dot = psum[buf][lane][0] + psum[buf][lane][1];
                const float ns  = fast_tanh(drv + dot);
                const float sn  = (1.0f - LEAK) * s_prev + LEAK * ns;
                s_prev = sn;
                g_states[(size_t)t * N_RES + myrow] = sn;
                // publish {tag=t+1, val=sn} — one coalesced 128B line store
                const unsigned long long pkt =
                    ((unsigned long long)(unsigned)(t + 1) << 32) |
                    (unsigned long long)__float_as_uint(sn);
                st_rlx64(&g_line[(t + 1) & 1][blockIdx.x][lane], pkt);
                // prefetch next drive AFTER the publish
                const int tn = (t + 1 < T_STEPS) ? t + 1 : t;
                drv = __ldcs(&g_drive[(size_t)tn * N_RES + myrow]);
            }
        }
    }
}

// ---------------------------------------------------------------------------
// Readout: out[T, 64] = states[T, 2048] @ w_out[64, 2048]^T + b_out
__global__ void __launch_bounds__(256)
readout_kernel(const float* __restrict__ wout,
               const float* __restrict__ bout,
               float* __restrict__ out)
{
    __shared__ float As[64][65];
    __shared__ float Bs[64][65];

    const int t0  = blockIdx.x * 64;
    const int tid = threadIdx.x;
    const int tx  = tid & 15;
    const int ty  = tid >> 4;

    float acc[4][4];
#pragma unroll
    for (int i = 0; i < 4; ++i)
#pragma unroll
        for (int j = 0; j < 4; ++j) acc[i][j] = 0.0f;

    for (int k0 = 0; k0 < N_RES; k0 += 64) {
#pragma unroll
        for (int i = tid; i < 1024; i += 256) {
            const int r  = i >> 4;
            const int c4 = (i & 15) * 4;
            const float4 v = *(const float4*)&g_states[(size_t)(t0 + r) * N_RES + k0 + c4];
            As[c4 + 0][r] = v.x; As[c4 + 1][r] = v.y;
            As[c4 + 2][r] = v.z; As[c4 + 3][r] = v.w;
            const float4 w = *(const float4*)&wout[(size_t)r * N_RES + k0 + c4];
            Bs[c4 + 0][r] = w.x; Bs[c4 + 1][r] = w.y;
            Bs[c4 + 2][r] = w.z; Bs[c4 + 3][r] = w.w;
        }
        __syncthreads();

#pragma unroll
        for (int kk = 0; kk < 64; ++kk) {
            float a[4], b[4];
#pragma unroll
            for (int j = 0; j < 4; ++j) { a[j] = As[kk][4 * ty + j]; b[j] = Bs[kk][4 * tx + j]; }
#pragma unroll
            for (int i = 0; i < 4; ++i)
#pragma unroll
                for (int j = 0; j < 4; ++j) acc[i][j] = fmaf(a[i], b[j], acc[i][j]);
        }
        __syncthreads();
    }

#pragma unroll
    for (int i = 0; i < 4; ++i)
#pragma unroll
        for (int j = 0; j < 4; ++j)
            out[(size_t)(t0 + 4 * ty + i) * D_OUT + 4 * tx + j] = acc[i][j] + bout[4 * tx + j];
}

// ---------------------------------------------------------------------------
extern "C" void kernel_launch(void* const* d_in, const int* in_sizes, int n_in,
                              void* d_out, int out_size)
{
    const float* u     = (const float*)d_in[0];
    const float* noise = (const float*)d_in[1];
    const float* W_in  = (const float*)d_in[2];
    const float* W     = (const float*)d_in[3];
    const float* w_out = (const float*)d_in[4];
    const float* b_out = (const float*)d_in[5];
    float*       out   = (float*)d_out;

    init_kernel<<<16, 256>>>();
    {
        dim3 g(N_RES / 256, T_STEPS / 32);
        drive_kernel<<<g, 256>>>(u, noise, W_in);
    }
    reservoir_kernel<<<GRID_P, THREADS_P>>>(W);
    readout_kernel<<<T_STEPS / 64, 256>>>(w_out, b_out, out);
}